// round 13
// baseline (speedup 1.0000x reference)
#include <cuda_runtime.h>
#include <math.h>

#define L 16
#define C 128
#define HH 96
#define WW 96
#define HW (HH*WW)          // 9216
#define CHW (C*HW)          // 1179648

#define CG 16               // channels per group (pass A)
#define NPART (C/CG)        // 8
#define RPB 16              // rows per block
#define TPB 192             // 16 rows x 12 strips of 8 px

typedef unsigned long long ull;

// ---------------- scratch (device globals; no runtime allocation) -------------
__device__ float2 g_weff2[C*25];          // [c][k] folded conv weights, dup {w,w}
__device__ float  g_WvT[C*C];             // WvT[k][c] = Wv[c][k]
__device__ float  g_u[NPART*L*5*HW];      // partial horiz conv [part][l][kh][hw] 23.6MB
__device__ float  g_Ak[L*HW];             // pre-softmax scores [j][hw]
__device__ float  g_xbar[C*HW];           // softmax-weighted frame average [c][hw]

// ---------------- 1. fold Wk into the 25 per-tap projection vectors ----------
// weff[c][k] = sum_d Wa[C+d][k] * Wk[d][c]   (bk/ba/Wq/bq all cancel in softmax)
__global__ void fold_kernel(const float* __restrict__ Wk,
                            const float* __restrict__ Wa) {
    int k = blockIdx.x;      // 0..24
    int c = threadIdx.x;     // 0..127
    float acc = 0.f;
    #pragma unroll 4
    for (int d = 0; d < C; d++)
        acc += Wa[(C + d) * 25 + k] * Wk[d * C + c];
    g_weff2[c * 25 + k] = make_float2(acc, acc);
}

// ---------------- 2a/2b. transpose Wv (split to position convh at capture idx 3)
__global__ void transpose_wv_a(const float* __restrict__ Wv) {
    int k = blockIdx.x;                // 0..63
    int c = threadIdx.x;
    g_WvT[k * C + c] = Wv[c * C + k];
}
__global__ void transpose_wv_b(const float* __restrict__ Wv) {
    int k = 64 + blockIdx.x;           // 64..127
    int c = threadIdx.x;
    g_WvT[k * C + c] = Wv[c * C + k];
}

// ---------------- 3. Pass A: fused projection + HORIZONTAL 5-tap conv --------
// u[part][l][kh][h][w] = sum_{c in part} sum_kw weff[c][kh*5+kw] * x[l][c][h][w+kw-2]
// kh is SPLIT across blocks (3/2) to cut accumulator registers (<=24) so 5
// blocks/SM = 30 warps/SM. Aligned data pairs come straight from LDG.64 (no
// movs); only the 5 misaligned pairs are constructed.
template<int NKH>
__device__ __forceinline__ void convh_body(const float* __restrict__ xb,
                                           const ull* __restrict__ ws,
                                           float* __restrict__ ub,
                                           bool led, bool red) {
    ull acc[NKH][4];
    #pragma unroll
    for (int kh = 0; kh < NKH; kh++)
        #pragma unroll
        for (int j = 0; j < 4; j++) acc[kh][j] = 0ull;

    #pragma unroll 1
    for (int c = 0; c < CG; c++) {
        const float* xr = xb + c * HW;
        ull a0 = led ? 0ull : *(const ull*)(xr);
        ull a1 = *(const ull*)(xr + 2);
        ull a2 = *(const ull*)(xr + 4);
        ull a3 = *(const ull*)(xr + 6);
        ull a4 = *(const ull*)(xr + 8);
        ull a5 = red ? 0ull : *(const ull*)(xr + 10);
        ull a[6] = {a0, a1, a2, a3, a4, a5};

        float lo[6], hi[6];
        #pragma unroll
        for (int i = 0; i < 6; i++)
            asm("mov.b64 {%0, %1}, %2;" : "=f"(lo[i]), "=f"(hi[i]) : "l"(a[i]));
        ull m[5];
        #pragma unroll
        for (int j = 0; j < 5; j++)
            asm("mov.b64 %0, {%1, %2};" : "=l"(m[j]) : "f"(hi[j]), "f"(lo[j + 1]));

        const ull* wc = ws + c * (NKH * 5);
        #pragma unroll
        for (int kh = 0; kh < NKH; kh++) {
            ull w0v = wc[kh * 5 + 0];
            ull w1v = wc[kh * 5 + 1];
            ull w2v = wc[kh * 5 + 2];
            ull w3v = wc[kh * 5 + 3];
            ull w4v = wc[kh * 5 + 4];
            #pragma unroll
            for (int j = 0; j < 4; j++) {
                asm("fma.rn.f32x2 %0, %1, %2, %0;" : "+l"(acc[kh][j]) : "l"(w0v), "l"(a[j]));
                asm("fma.rn.f32x2 %0, %1, %2, %0;" : "+l"(acc[kh][j]) : "l"(w1v), "l"(m[j]));
                asm("fma.rn.f32x2 %0, %1, %2, %0;" : "+l"(acc[kh][j]) : "l"(w2v), "l"(a[j + 1]));
                asm("fma.rn.f32x2 %0, %1, %2, %0;" : "+l"(acc[kh][j]) : "l"(w3v), "l"(m[j + 1]));
                asm("fma.rn.f32x2 %0, %1, %2, %0;" : "+l"(acc[kh][j]) : "l"(w4v), "l"(a[j + 2]));
            }
        }
    }

    #pragma unroll
    for (int kh = 0; kh < NKH; kh++) {
        #pragma unroll
        for (int j = 0; j < 4; j++) {
            float x0, x1;
            asm("mov.b64 {%0, %1}, %2;" : "=f"(x0), "=f"(x1) : "l"(acc[kh][j]));
            *(float2*)(ub + kh * HW + 2 * j) = make_float2(x0, x1);
        }
    }
}

__global__ void __launch_bounds__(TPB, 5) convh_kernel(const float* __restrict__ x) {
    __shared__ ull ws2[CG * 15];   // this half's duplicated weights (max 15 taps)
    const int tid    = threadIdx.x;
    const int rowblk = blockIdx.x;       // 0..5
    const int py     = blockIdx.y;       // 0..15 = part*2 + half
    const int part   = py >> 1;
    const int half   = py & 1;
    const int l      = blockIdx.z;       // 0..15
    const int row    = tid / 12;         // 0..15
    const int strip  = tid - row * 12;   // 0..11
    const int w0     = strip * 8;
    const int h      = rowblk * RPB + row;
    const int c0     = part * CG;

    const ull* wsrc = (const ull*)g_weff2;
    const bool led = (strip == 0);
    const bool red = (strip == 11);
    const float* xb = x + (size_t)l * CHW + (size_t)c0 * HW + h * WW + (w0 - 2);

    if (half == 0) {
        // taps 0..14 (kh 0,1,2)
        #pragma unroll
        for (int i = tid; i < CG * 15; i += TPB)
            ws2[i] = wsrc[(c0 + i / 15) * 25 + (i % 15)];
        __syncthreads();
        float* ub = g_u + (((size_t)part * L + l) * 5) * HW + h * WW + w0;
        convh_body<3>(xb, ws2, ub, led, red);
    } else {
        // taps 15..24 (kh 3,4)
        #pragma unroll
        for (int i = tid; i < CG * 10; i += TPB)
            ws2[i] = wsrc[(c0 + i / 10) * 25 + 15 + (i % 10)];
        __syncthreads();
        float* ub = g_u + (((size_t)part * L + l) * 5 + 3) * HW + h * WW + w0;
        convh_body<2>(xb, ws2, ub, led, red);
    }
}

// ---------------- 4. Pass B: vertical 5-tap + partial-sum -> Ak --------------
// Ak[l][hw] = sum_part sum_kh u[part][l][kh][h+kh-2][w].  u is L2-resident.
__global__ void akb_kernel() {
    const int l  = blockIdx.y;
    const int p4 = (blockIdx.x * 256 + threadIdx.x) * 4;
    const int h  = p4 / WW;
    const int w  = p4 - h * WW;

    float4 acc = make_float4(0.f, 0.f, 0.f, 0.f);
    #pragma unroll
    for (int kh = 0; kh < 5; kh++) {
        const int hh = h + kh - 2;
        if ((unsigned)hh >= HH) continue;
        #pragma unroll
        for (int part = 0; part < NPART; part++) {
            const float4 v = *(const float4*)&g_u[
                (((size_t)part * L + l) * 5 + kh) * HW + hh * WW + w];
            acc.x += v.x; acc.y += v.y; acc.z += v.z; acc.w += v.w;
        }
    }
    *(float4*)&g_Ak[l * HW + p4] = acc;
}

// ---------------- 5. fused softmax + xbar ------------------------------------
// xbar[c][hw] = sum_j softmax_j(Ak)[j][hw] * x[j][c][hw]
__global__ void xbarsm_kernel(const float* __restrict__ x) {
    const int p4    = blockIdx.x * 1024 + threadIdx.x * 4;   // pixel base
    const int cbase = blockIdx.y * 4;

    float4 a[L];
    #pragma unroll
    for (int j = 0; j < L; j++)
        a[j] = *(const float4*)&g_Ak[j * HW + p4];

    float4 mx = a[0];
    #pragma unroll
    for (int j = 1; j < L; j++) {
        mx.x = fmaxf(mx.x, a[j].x); mx.y = fmaxf(mx.y, a[j].y);
        mx.z = fmaxf(mx.z, a[j].z); mx.w = fmaxf(mx.w, a[j].w);
    }
    float4 s = make_float4(0.f, 0.f, 0.f, 0.f);
    #pragma unroll
    for (int j = 0; j < L; j++) {
        a[j].x = __expf(a[j].x - mx.x); s.x += a[j].x;
        a[j].y = __expf(a[j].y - mx.y); s.y += a[j].y;
        a[j].z = __expf(a[j].z - mx.z); s.z += a[j].z;
        a[j].w = __expf(a[j].w - mx.w); s.w += a[j].w;
    }
    const float4 inv = make_float4(1.f / s.x, 1.f / s.y, 1.f / s.z, 1.f / s.w);

    float4 acc[4];
    #pragma unroll
    for (int i = 0; i < 4; i++) acc[i] = make_float4(0.f, 0.f, 0.f, 0.f);

    #pragma unroll
    for (int j = 0; j < L; j++) {
        const float* xj = x + (size_t)(j * C + cbase) * HW + p4;
        #pragma unroll
        for (int i = 0; i < 4; i++) {
            const float4 xv = *(const float4*)&xj[i * HW];
            acc[i].x += a[j].x * xv.x;
            acc[i].y += a[j].y * xv.y;
            acc[i].z += a[j].z * xv.z;
            acc[i].w += a[j].w * xv.w;
        }
    }
    #pragma unroll
    for (int i = 0; i < 4; i++) {
        float4 r = make_float4(acc[i].x * inv.x, acc[i].y * inv.y,
                               acc[i].z * inv.z, acc[i].w * inv.w);
        *(float4*)&g_xbar[(cbase + i) * HW + p4] = r;
    }
}

// ---------------- 6. out[f][c][hw] = Wv . xbar + bv, broadcast to 16 frames --
__global__ void gemm_out_kernel(const float* __restrict__ bv,
                                float* __restrict__ out) {
    __shared__ float wv_s[16][64];
    __shared__ float xb_s[16][64];
    const int tid = threadIdx.y * 16 + threadIdx.x;
    const int pG = blockIdx.x * 64;
    const int cG = blockIdx.y * 64;

    const int sr   = tid >> 4;          // 0..15
    const int sc4  = (tid & 15) * 4;    // 0..60

    float acc[4][4];
    #pragma unroll
    for (int i = 0; i < 4; i++)
        #pragma unroll
        for (int j = 0; j < 4; j++) acc[i][j] = 0.f;

    for (int k0 = 0; k0 < C; k0 += 16) {
        *(float4*)&wv_s[sr][sc4] = *(const float4*)&g_WvT[(k0 + sr) * C + cG + sc4];
        *(float4*)&xb_s[sr][sc4] = *(const float4*)&g_xbar[(k0 + sr) * HW + pG + sc4];
        __syncthreads();
        #pragma unroll
        for (int kk = 0; kk < 16; kk++) {
            const float4 wv4 = *(const float4*)&wv_s[kk][threadIdx.y * 4];
            const float4 xb4 = *(const float4*)&xb_s[kk][threadIdx.x * 4];
            float wr[4] = {wv4.x, wv4.y, wv4.z, wv4.w};
            float xr[4] = {xb4.x, xb4.y, xb4.z, xb4.w};
            #pragma unroll
            for (int ci = 0; ci < 4; ci++)
                #pragma unroll
                for (int pi = 0; pi < 4; pi++)
                    acc[ci][pi] += wr[ci] * xr[pi];
        }
        __syncthreads();
    }

    const int c0 = cG + threadIdx.y * 4;
    const int p0 = pG + threadIdx.x * 4;
    #pragma unroll
    for (int ci = 0; ci < 4; ci++) {
        float b = bv[c0 + ci];
        float4 v = make_float4(acc[ci][0] + b, acc[ci][1] + b,
                               acc[ci][2] + b, acc[ci][3] + b);
        #pragma unroll
        for (int f = 0; f < L; f++)
            *(float4*)&out[(size_t)(f * C + c0 + ci) * HW + p0] = v;
    }
}

// ---------------- launch -----------------------------------------------------
extern "C" void kernel_launch(void* const* d_in, const int* in_sizes, int n_in,
                              void* d_out, int out_size) {
    const float* x  = (const float*)d_in[0];
    // d_in[1]=Wq, d_in[2]=bq unused (cancel in softmax over j)
    const float* Wk = (const float*)d_in[3];
    // d_in[4]=bk unused (border bias map is j-independent -> cancels)
    const float* Wv = (const float*)d_in[5];
    const float* bv = (const float*)d_in[6];
    const float* Wa = (const float*)d_in[7];
    // d_in[8]=ba unused (cancels)
    float* out = (float*)d_out;

    // order chosen so the single ncu capture (launch index 3) profiles convh
    fold_kernel<<<25, 128>>>(Wk, Wa);                         // 0
    transpose_wv_a<<<64, 128>>>(Wv);                          // 1
    transpose_wv_b<<<64, 128>>>(Wv);                          // 2
    convh_kernel<<<dim3(HH / RPB, NPART * 2, L), TPB>>>(x);   // 3  <- profiled (1536 blocks)
    akb_kernel<<<dim3(9, L), 256>>>();                        // 4
    xbarsm_kernel<<<dim3(9, 32), 256>>>(x);                   // 5
    gemm_out_kernel<<<dim3(HW / 64, 2), dim3(16, 16)>>>(bv, out);  // 6
}

// round 15
// speedup vs baseline: 1.0182x; 1.0182x over previous
#include <cuda_runtime.h>
#include <math.h>

#define L 16
#define C 128
#define HH 96
#define WW 96
#define HW (HH*WW)          // 9216
#define CHW (C*HW)          // 1179648

#define CG 16               // channels per group (pass A)
#define NPART (C/CG)        // 8
#define RPB 16              // rows per block
#define TPB 192             // 16 rows x 12 strips of 8 px

typedef unsigned long long ull;

// ---------------- scratch (device globals; no runtime allocation) -------------
__device__ float2 g_weff2[C*25];          // [c][k] folded conv weights, dup {w,w}
__device__ float  g_WvT[C*C];             // WvT[k][c] = Wv[c][k]
__device__ float  g_u[NPART*L*5*HW];      // partial horiz conv [part][l][kh][hw] 23.6MB
__device__ float  g_Ak[L*HW];             // pre-softmax scores [j][hw]
__device__ float  g_xbar[C*HW];           // softmax-weighted frame average [c][hw]

// ---------------- 1. fold Wk into the 25 per-tap projection vectors ----------
// weff[c][k] = sum_d Wa[C+d][k] * Wk[d][c]   (bk/ba/Wq/bq all cancel in softmax)
__global__ void fold_kernel(const float* __restrict__ Wk,
                            const float* __restrict__ Wa) {
    int k = blockIdx.x;      // 0..24
    int c = threadIdx.x;     // 0..127
    float acc = 0.f;
    #pragma unroll 4
    for (int d = 0; d < C; d++)
        acc += Wa[(C + d) * 25 + k] * Wk[d * C + c];
    g_weff2[c * 25 + k] = make_float2(acc, acc);
}

// ---------------- 2a/2b. transpose Wv (split to position convh at capture idx 3)
__global__ void transpose_wv_a(const float* __restrict__ Wv) {
    int k = blockIdx.x;                // 0..63
    int c = threadIdx.x;
    g_WvT[k * C + c] = Wv[c * C + k];
}
__global__ void transpose_wv_b(const float* __restrict__ Wv) {
    int k = 64 + blockIdx.x;           // 64..127
    int c = threadIdx.x;
    g_WvT[k * C + c] = Wv[c * C + k];
}

// ---------------- 3. Pass A: fused projection + HORIZONTAL 5-tap conv --------
// u[part][l][kh][h][w] = sum_{c in part} sum_kw weff[c][kh*5+kw] * x[l][c][h][w+kw-2]
// (exact R12 configuration: 40.3us measured)
__global__ void __launch_bounds__(TPB, 4) convh_kernel(const float* __restrict__ x) {
    __shared__ ull ws2[CG * 25];   // this group's duplicated weights, 3.2 KB
    const int tid    = threadIdx.x;
    const int rowblk = blockIdx.x;      // 0..5
    const int part   = blockIdx.y;      // 0..7
    const int l      = blockIdx.z;      // 0..15
    const int row    = tid / 12;        // 0..15
    const int strip  = tid - row * 12;  // 0..11
    const int w0     = strip * 8;
    const int h      = rowblk * RPB + row;
    const int c0     = part * CG;

    const ull* wsrc = (const ull*)g_weff2;
    #pragma unroll
    for (int i = tid; i < CG * 25; i += TPB) {
        int c = i / 25, k = i - c * 25;
        ws2[i] = wsrc[(c0 + c) * 25 + k];
    }
    __syncthreads();

    ull acc[5][4];
    #pragma unroll
    for (int kh = 0; kh < 5; kh++)
        #pragma unroll
        for (int j = 0; j < 4; j++) acc[kh][j] = 0ull;

    const bool led = (strip == 0);
    const bool red = (strip == 11);
    const float* xb = x + (size_t)l * CHW + (size_t)c0 * HW + h * WW + (w0 - 2);

    #pragma unroll 2
    for (int c = 0; c < CG; c++) {
        const float* xr = xb + c * HW;
        float2 f0 = led ? make_float2(0.f, 0.f) : *(const float2*)(xr);
        float2 f1 = *(const float2*)(xr + 2);
        float2 f2 = *(const float2*)(xr + 4);
        float2 f3 = *(const float2*)(xr + 6);
        float2 f4 = *(const float2*)(xr + 8);
        float2 f5 = red ? make_float2(0.f, 0.f) : *(const float2*)(xr + 10);

        ull a[6], m[5];
        asm("mov.b64 %0, {%1, %2};" : "=l"(a[0]) : "f"(f0.x), "f"(f0.y));
        asm("mov.b64 %0, {%1, %2};" : "=l"(a[1]) : "f"(f1.x), "f"(f1.y));
        asm("mov.b64 %0, {%1, %2};" : "=l"(a[2]) : "f"(f2.x), "f"(f2.y));
        asm("mov.b64 %0, {%1, %2};" : "=l"(a[3]) : "f"(f3.x), "f"(f3.y));
        asm("mov.b64 %0, {%1, %2};" : "=l"(a[4]) : "f"(f4.x), "f"(f4.y));
        asm("mov.b64 %0, {%1, %2};" : "=l"(a[5]) : "f"(f5.x), "f"(f5.y));
        asm("mov.b64 %0, {%1, %2};" : "=l"(m[0]) : "f"(f0.y), "f"(f1.x));
        asm("mov.b64 %0, {%1, %2};" : "=l"(m[1]) : "f"(f1.y), "f"(f2.x));
        asm("mov.b64 %0, {%1, %2};" : "=l"(m[2]) : "f"(f2.y), "f"(f3.x));
        asm("mov.b64 %0, {%1, %2};" : "=l"(m[3]) : "f"(f3.y), "f"(f4.x));
        asm("mov.b64 %0, {%1, %2};" : "=l"(m[4]) : "f"(f4.y), "f"(f5.x));

        const ull* wc = &ws2[c * 25];
        #pragma unroll
        for (int kh = 0; kh < 5; kh++) {
            ull w0v = wc[kh * 5 + 0];
            ull w1v = wc[kh * 5 + 1];
            ull w2v = wc[kh * 5 + 2];
            ull w3v = wc[kh * 5 + 3];
            ull w4v = wc[kh * 5 + 4];
            #pragma unroll
            for (int j = 0; j < 4; j++) {
                asm("fma.rn.f32x2 %0, %1, %2, %0;" : "+l"(acc[kh][j]) : "l"(w0v), "l"(a[j]));
                asm("fma.rn.f32x2 %0, %1, %2, %0;" : "+l"(acc[kh][j]) : "l"(w1v), "l"(m[j]));
                asm("fma.rn.f32x2 %0, %1, %2, %0;" : "+l"(acc[kh][j]) : "l"(w2v), "l"(a[j + 1]));
                asm("fma.rn.f32x2 %0, %1, %2, %0;" : "+l"(acc[kh][j]) : "l"(w3v), "l"(m[j + 1]));
                asm("fma.rn.f32x2 %0, %1, %2, %0;" : "+l"(acc[kh][j]) : "l"(w4v), "l"(a[j + 2]));
            }
        }
    }

    float* ub = g_u + (((size_t)part * L + l) * 5) * HW + h * WW + w0;
    #pragma unroll
    for (int kh = 0; kh < 5; kh++) {
        #pragma unroll
        for (int j = 0; j < 4; j++) {
            float lo, hi;
            asm("mov.b64 {%0, %1}, %2;" : "=f"(lo), "=f"(hi) : "l"(acc[kh][j]));
            *(float2*)(ub + kh * HW + 2 * j) = make_float2(lo, hi);
        }
    }
}

// ---------------- 4. Pass B: vertical 5-tap + partial-sum -> Ak --------------
__global__ void akb_kernel() {
    const int l  = blockIdx.y;
    const int p4 = (blockIdx.x * 256 + threadIdx.x) * 4;
    const int h  = p4 / WW;
    const int w  = p4 - h * WW;

    float4 acc = make_float4(0.f, 0.f, 0.f, 0.f);
    #pragma unroll
    for (int kh = 0; kh < 5; kh++) {
        const int hh = h + kh - 2;
        if ((unsigned)hh >= HH) continue;
        #pragma unroll
        for (int part = 0; part < NPART; part++) {
            const float4 v = *(const float4*)&g_u[
                (((size_t)part * L + l) * 5 + kh) * HW + hh * WW + w];
            acc.x += v.x; acc.y += v.y; acc.z += v.z; acc.w += v.w;
        }
    }
    *(float4*)&g_Ak[l * HW + p4] = acc;
}

// ---------------- 5. fused softmax + xbar ------------------------------------
__global__ void xbarsm_kernel(const float* __restrict__ x) {
    const int p4    = blockIdx.x * 1024 + threadIdx.x * 4;   // pixel base
    const int cbase = blockIdx.y * 4;

    float4 a[L];
    #pragma unroll
    for (int j = 0; j < L; j++)
        a[j] = *(const float4*)&g_Ak[j * HW + p4];

    float4 mx = a[0];
    #pragma unroll
    for (int j = 1; j < L; j++) {
        mx.x = fmaxf(mx.x, a[j].x); mx.y = fmaxf(mx.y, a[j].y);
        mx.z = fmaxf(mx.z, a[j].z); mx.w = fmaxf(mx.w, a[j].w);
    }
    float4 s = make_float4(0.f, 0.f, 0.f, 0.f);
    #pragma unroll
    for (int j = 0; j < L; j++) {
        a[j].x = __expf(a[j].x - mx.x); s.x += a[j].x;
        a[j].y = __expf(a[j].y - mx.y); s.y += a[j].y;
        a[j].z = __expf(a[j].z - mx.z); s.z += a[j].z;
        a[j].w = __expf(a[j].w - mx.w); s.w += a[j].w;
    }
    const float4 inv = make_float4(1.f / s.x, 1.f / s.y, 1.f / s.z, 1.f / s.w);

    float4 acc[4];
    #pragma unroll
    for (int i = 0; i < 4; i++) acc[i] = make_float4(0.f, 0.f, 0.f, 0.f);

    #pragma unroll
    for (int j = 0; j < L; j++) {
        const float* xj = x + (size_t)(j * C + cbase) * HW + p4;
        #pragma unroll
        for (int i = 0; i < 4; i++) {
            const float4 xv = *(const float4*)&xj[i * HW];
            acc[i].x += a[j].x * xv.x;
            acc[i].y += a[j].y * xv.y;
            acc[i].z += a[j].z * xv.z;
            acc[i].w += a[j].w * xv.w;
        }
    }
    #pragma unroll
    for (int i = 0; i < 4; i++) {
        float4 r = make_float4(acc[i].x * inv.x, acc[i].y * inv.y,
                               acc[i].z * inv.z, acc[i].w * inv.w);
        *(float4*)&g_xbar[(cbase + i) * HW + p4] = r;
    }
}

// ---------------- 6. out[f][c][hw] = Wv . xbar + bv --------------------------
// blockIdx.z splits the 16-frame broadcast (frames z*8..z*8+7): compute is
// redundant (trivial) but store streams spread over 2x blocks. Streaming
// stores (st.global.cs) keep the 75.5MB output from polluting L2.
__global__ void gemm_out_kernel(const float* __restrict__ bv,
                                float* __restrict__ out) {
    __shared__ float wv_s[16][64];
    __shared__ float xb_s[16][64];
    const int tid = threadIdx.y * 16 + threadIdx.x;
    const int pG = blockIdx.x * 64;
    const int cG = blockIdx.y * 64;
    const int f0 = blockIdx.z * 8;

    const int sr   = tid >> 4;          // 0..15
    const int sc4  = (tid & 15) * 4;    // 0..60

    float acc[4][4];
    #pragma unroll
    for (int i = 0; i < 4; i++)
        #pragma unroll
        for (int j = 0; j < 4; j++) acc[i][j] = 0.f;

    for (int k0 = 0; k0 < C; k0 += 16) {
        *(float4*)&wv_s[sr][sc4] = *(const float4*)&g_WvT[(k0 + sr) * C + cG + sc4];
        *(float4*)&xb_s[sr][sc4] = *(const float4*)&g_xbar[(k0 + sr) * HW + pG + sc4];
        __syncthreads();
        #pragma unroll
        for (int kk = 0; kk < 16; kk++) {
            const float4 wv4 = *(const float4*)&wv_s[kk][threadIdx.y * 4];
            const float4 xb4 = *(const float4*)&xb_s[kk][threadIdx.x * 4];
            float wr[4] = {wv4.x, wv4.y, wv4.z, wv4.w};
            float xr[4] = {xb4.x, xb4.y, xb4.z, xb4.w};
            #pragma unroll
            for (int ci = 0; ci < 4; ci++)
                #pragma unroll
                for (int pi = 0; pi < 4; pi++)
                    acc[ci][pi] += wr[ci] * xr[pi];
        }
        __syncthreads();
    }

    const int c0 = cG + threadIdx.y * 4;
    const int p0 = pG + threadIdx.x * 4;
    #pragma unroll
    for (int ci = 0; ci < 4; ci++) {
        float b = bv[c0 + ci];
        float4 v = make_float4(acc[ci][0] + b, acc[ci][1] + b,
                               acc[ci][2] + b, acc[ci][3] + b);
        #pragma unroll
        for (int f = 0; f < 8; f++) {
            float* dst = &out[(size_t)((f0 + f) * C + c0 + ci) * HW + p0];
            asm volatile("st.global.cs.v4.f32 [%0], {%1, %2, %3, %4};"
                         :: "l"(dst), "f"(v.x), "f"(v.y), "f"(v.z), "f"(v.w)
                         : "memory");
        }
    }
}

// ---------------- launch -----------------------------------------------------
extern "C" void kernel_launch(void* const* d_in, const int* in_sizes, int n_in,
                              void* d_out, int out_size) {
    const float* x  = (const float*)d_in[0];
    // d_in[1]=Wq, d_in[2]=bq unused (cancel in softmax over j)
    const float* Wk = (const float*)d_in[3];
    // d_in[4]=bk unused (border bias map is j-independent -> cancels)
    const float* Wv = (const float*)d_in[5];
    const float* bv = (const float*)d_in[6];
    const float* Wa = (const float*)d_in[7];
    // d_in[8]=ba unused (cancels)
    float* out = (float*)d_out;

    // order chosen so the single ncu capture (launch index 3) profiles convh
    fold_kernel<<<25, 128>>>(Wk, Wa);                         // 0
    transpose_wv_a<<<64, 128>>>(Wv);                          // 1
    transpose_wv_b<<<64, 128>>>(Wv);                          // 2
    convh_kernel<<<dim3(HH / RPB, NPART, L), TPB>>>(x);       // 3  <- profiled (768 blocks)
    akb_kernel<<<dim3(9, L), 256>>>();                        // 4
    xbarsm_kernel<<<dim3(9, 32), 256>>>(x);                   // 5
    gemm_out_kernel<<<dim3(HW / 64, 2, 2), dim3(16, 16)>>>(bv, out);  // 6
}

// round 16
// speedup vs baseline: 1.0997x; 1.0800x over previous
#include <cuda_runtime.h>
#include <math.h>

#define L 16
#define C 128
#define HH 96
#define WW 96
#define HW (HH*WW)          // 9216
#define CHW (C*HW)          // 1179648

#define CG 16               // channels per group (pass A)
#define NPART (C/CG)        // 8
#define RPB 16              // rows per block
#define TPB 192             // 16 rows x 12 strips of 8 px

typedef unsigned long long ull;

// ---------------- scratch (device globals; no runtime allocation) -------------
__device__ float2 g_weff2[C*25];          // [c][k] folded conv weights, dup {w,w}
__device__ float  g_WvT[C*C];             // WvT[k][c] = Wv[c][k]
__device__ float  g_u[NPART*L*5*HW];      // partial horiz conv [part][l][kh][hw] 23.6MB
__device__ float  g_Ak[L*HW];             // pre-softmax scores [j][hw]
__device__ float  g_xbar[C*HW];           // softmax-weighted frame average [c][hw]

// ---------------- 1. fold Wk into the 25 per-tap projection vectors ----------
// weff[c][k] = sum_d Wa[C+d][k] * Wk[d][c]   (bk/ba/Wq/bq all cancel in softmax)
__global__ void fold_kernel(const float* __restrict__ Wk,
                            const float* __restrict__ Wa) {
    int k = blockIdx.x;      // 0..24
    int c = threadIdx.x;     // 0..127
    float acc = 0.f;
    #pragma unroll 4
    for (int d = 0; d < C; d++)
        acc += Wa[(C + d) * 25 + k] * Wk[d * C + c];
    g_weff2[c * 25 + k] = make_float2(acc, acc);
}

// ---------------- 2a/2b. transpose Wv (split so akb sits at capture idx 3) ---
__global__ void transpose_wv_a(const float* __restrict__ Wv) {
    int k = blockIdx.x;                // 0..63
    int c = threadIdx.x;
    g_WvT[k * C + c] = Wv[c * C + k];
}
__global__ void transpose_wv_b(const float* __restrict__ Wv) {
    int k = 64 + blockIdx.x;           // 64..127
    int c = threadIdx.x;
    g_WvT[k * C + c] = Wv[c * C + k];
}

// ---------------- 3. Pass A: fused projection + HORIZONTAL 5-tap conv --------
// u[part][l][kh][h][w] = sum_{c in part} sum_kw weff[c][kh*5+kw] * x[l][c][h][w+kw-2]
// (exact R12 configuration: 40.3us measured)
__global__ void __launch_bounds__(TPB, 4) convh_kernel(const float* __restrict__ x) {
    __shared__ ull ws2[CG * 25];   // this group's duplicated weights, 3.2 KB
    const int tid    = threadIdx.x;
    const int rowblk = blockIdx.x;      // 0..5
    const int part   = blockIdx.y;      // 0..7
    const int l      = blockIdx.z;      // 0..15
    const int row    = tid / 12;        // 0..15
    const int strip  = tid - row * 12;  // 0..11
    const int w0     = strip * 8;
    const int h      = rowblk * RPB + row;
    const int c0     = part * CG;

    const ull* wsrc = (const ull*)g_weff2;
    #pragma unroll
    for (int i = tid; i < CG * 25; i += TPB) {
        int c = i / 25, k = i - c * 25;
        ws2[i] = wsrc[(c0 + c) * 25 + k];
    }
    __syncthreads();

    ull acc[5][4];
    #pragma unroll
    for (int kh = 0; kh < 5; kh++)
        #pragma unroll
        for (int j = 0; j < 4; j++) acc[kh][j] = 0ull;

    const bool led = (strip == 0);
    const bool red = (strip == 11);
    const float* xb = x + (size_t)l * CHW + (size_t)c0 * HW + h * WW + (w0 - 2);

    #pragma unroll 2
    for (int c = 0; c < CG; c++) {
        const float* xr = xb + c * HW;
        float2 f0 = led ? make_float2(0.f, 0.f) : *(const float2*)(xr);
        float2 f1 = *(const float2*)(xr + 2);
        float2 f2 = *(const float2*)(xr + 4);
        float2 f3 = *(const float2*)(xr + 6);
        float2 f4 = *(const float2*)(xr + 8);
        float2 f5 = red ? make_float2(0.f, 0.f) : *(const float2*)(xr + 10);

        ull a[6], m[5];
        asm("mov.b64 %0, {%1, %2};" : "=l"(a[0]) : "f"(f0.x), "f"(f0.y));
        asm("mov.b64 %0, {%1, %2};" : "=l"(a[1]) : "f"(f1.x), "f"(f1.y));
        asm("mov.b64 %0, {%1, %2};" : "=l"(a[2]) : "f"(f2.x), "f"(f2.y));
        asm("mov.b64 %0, {%1, %2};" : "=l"(a[3]) : "f"(f3.x), "f"(f3.y));
        asm("mov.b64 %0, {%1, %2};" : "=l"(a[4]) : "f"(f4.x), "f"(f4.y));
        asm("mov.b64 %0, {%1, %2};" : "=l"(a[5]) : "f"(f5.x), "f"(f5.y));
        asm("mov.b64 %0, {%1, %2};" : "=l"(m[0]) : "f"(f0.y), "f"(f1.x));
        asm("mov.b64 %0, {%1, %2};" : "=l"(m[1]) : "f"(f1.y), "f"(f2.x));
        asm("mov.b64 %0, {%1, %2};" : "=l"(m[2]) : "f"(f2.y), "f"(f3.x));
        asm("mov.b64 %0, {%1, %2};" : "=l"(m[3]) : "f"(f3.y), "f"(f4.x));
        asm("mov.b64 %0, {%1, %2};" : "=l"(m[4]) : "f"(f4.y), "f"(f5.x));

        const ull* wc = &ws2[c * 25];
        #pragma unroll
        for (int kh = 0; kh < 5; kh++) {
            ull w0v = wc[kh * 5 + 0];
            ull w1v = wc[kh * 5 + 1];
            ull w2v = wc[kh * 5 + 2];
            ull w3v = wc[kh * 5 + 3];
            ull w4v = wc[kh * 5 + 4];
            #pragma unroll
            for (int j = 0; j < 4; j++) {
                asm("fma.rn.f32x2 %0, %1, %2, %0;" : "+l"(acc[kh][j]) : "l"(w0v), "l"(a[j]));
                asm("fma.rn.f32x2 %0, %1, %2, %0;" : "+l"(acc[kh][j]) : "l"(w1v), "l"(m[j]));
                asm("fma.rn.f32x2 %0, %1, %2, %0;" : "+l"(acc[kh][j]) : "l"(w2v), "l"(a[j + 1]));
                asm("fma.rn.f32x2 %0, %1, %2, %0;" : "+l"(acc[kh][j]) : "l"(w3v), "l"(m[j + 1]));
                asm("fma.rn.f32x2 %0, %1, %2, %0;" : "+l"(acc[kh][j]) : "l"(w4v), "l"(a[j + 2]));
            }
        }
    }

    float* ub = g_u + (((size_t)part * L + l) * 5) * HW + h * WW + w0;
    #pragma unroll
    for (int kh = 0; kh < 5; kh++) {
        #pragma unroll
        for (int j = 0; j < 4; j++) {
            float lo, hi;
            asm("mov.b64 {%0, %1}, %2;" : "=f"(lo), "=f"(hi) : "l"(acc[kh][j]));
            *(float2*)(ub + kh * HW + 2 * j) = make_float2(lo, hi);
        }
    }
}

// ---------------- 4. Pass B: vertical 5-tap + partial-sum -> Ak --------------
__global__ void akb_kernel() {
    const int l  = blockIdx.y;
    const int p4 = (blockIdx.x * 256 + threadIdx.x) * 4;
    const int h  = p4 / WW;
    const int w  = p4 - h * WW;

    float4 acc = make_float4(0.f, 0.f, 0.f, 0.f);
    #pragma unroll
    for (int kh = 0; kh < 5; kh++) {
        const int hh = h + kh - 2;
        if ((unsigned)hh >= HH) continue;
        #pragma unroll
        for (int part = 0; part < NPART; part++) {
            const float4 v = *(const float4*)&g_u[
                (((size_t)part * L + l) * 5 + kh) * HW + hh * WW + w];
            acc.x += v.x; acc.y += v.y; acc.z += v.z; acc.w += v.w;
        }
    }
    *(float4*)&g_Ak[l * HW + p4] = acc;
}

// ---------------- 5. fused softmax + xbar ------------------------------------
__global__ void xbarsm_kernel(const float* __restrict__ x) {
    const int p4    = blockIdx.x * 1024 + threadIdx.x * 4;   // pixel base
    const int cbase = blockIdx.y * 4;

    float4 a[L];
    #pragma unroll
    for (int j = 0; j < L; j++)
        a[j] = *(const float4*)&g_Ak[j * HW + p4];

    float4 mx = a[0];
    #pragma unroll
    for (int j = 1; j < L; j++) {
        mx.x = fmaxf(mx.x, a[j].x); mx.y = fmaxf(mx.y, a[j].y);
        mx.z = fmaxf(mx.z, a[j].z); mx.w = fmaxf(mx.w, a[j].w);
    }
    float4 s = make_float4(0.f, 0.f, 0.f, 0.f);
    #pragma unroll
    for (int j = 0; j < L; j++) {
        a[j].x = __expf(a[j].x - mx.x); s.x += a[j].x;
        a[j].y = __expf(a[j].y - mx.y); s.y += a[j].y;
        a[j].z = __expf(a[j].z - mx.z); s.z += a[j].z;
        a[j].w = __expf(a[j].w - mx.w); s.w += a[j].w;
    }
    const float4 inv = make_float4(1.f / s.x, 1.f / s.y, 1.f / s.z, 1.f / s.w);

    float4 acc[4];
    #pragma unroll
    for (int i = 0; i < 4; i++) acc[i] = make_float4(0.f, 0.f, 0.f, 0.f);

    #pragma unroll
    for (int j = 0; j < L; j++) {
        const float* xj = x + (size_t)(j * C + cbase) * HW + p4;
        #pragma unroll
        for (int i = 0; i < 4; i++) {
            const float4 xv = *(const float4*)&xj[i * HW];
            acc[i].x += a[j].x * xv.x;
            acc[i].y += a[j].y * xv.y;
            acc[i].z += a[j].z * xv.z;
            acc[i].w += a[j].w * xv.w;
        }
    }
    #pragma unroll
    for (int i = 0; i < 4; i++) {
        float4 r = make_float4(acc[i].x * inv.x, acc[i].y * inv.y,
                               acc[i].z * inv.z, acc[i].w * inv.w);
        *(float4*)&g_xbar[(cbase + i) * HW + p4] = r;
    }
}

// ---------------- 6. out[f][c][hw] = Wv . xbar + bv, broadcast to 16 frames --
// R12 structure (plain stores, no z-split) + double-buffered k-loop: next
// iteration's global loads are issued before this iteration's compute, hiding
// the 8 serialized DRAM round-trips of the R12 version. One barrier per iter.
__global__ void gemm_out_kernel(const float* __restrict__ bv,
                                float* __restrict__ out) {
    __shared__ float wv_s[2][16][64];
    __shared__ float xb_s[2][16][64];
    const int tid = threadIdx.y * 16 + threadIdx.x;
    const int pG = blockIdx.x * 64;
    const int cG = blockIdx.y * 64;

    const int sr   = tid >> 4;          // 0..15
    const int sc4  = (tid & 15) * 4;    // 0..60

    // preload stage 0
    float4 wv_in = *(const float4*)&g_WvT[sr * C + cG + sc4];
    float4 xb_in = *(const float4*)&g_xbar[sr * HW + pG + sc4];
    *(float4*)&wv_s[0][sr][sc4] = wv_in;
    *(float4*)&xb_s[0][sr][sc4] = xb_in;
    __syncthreads();

    float acc[4][4];
    #pragma unroll
    for (int i = 0; i < 4; i++)
        #pragma unroll
        for (int j = 0; j < 4; j++) acc[i][j] = 0.f;

    #pragma unroll
    for (int it = 0; it < 8; it++) {
        const int buf = it & 1;
        if (it < 7) {
            const int k0 = (it + 1) * 16;
            wv_in = *(const float4*)&g_WvT[(k0 + sr) * C + cG + sc4];
            xb_in = *(const float4*)&g_xbar[(k0 + sr) * HW + pG + sc4];
        }
        #pragma unroll
        for (int kk = 0; kk < 16; kk++) {
            const float4 wv4 = *(const float4*)&wv_s[buf][kk][threadIdx.y * 4];
            const float4 xb4 = *(const float4*)&xb_s[buf][kk][threadIdx.x * 4];
            float wr[4] = {wv4.x, wv4.y, wv4.z, wv4.w};
            float xr[4] = {xb4.x, xb4.y, xb4.z, xb4.w};
            #pragma unroll
            for (int ci = 0; ci < 4; ci++)
                #pragma unroll
                for (int pi = 0; pi < 4; pi++)
                    acc[ci][pi] += wr[ci] * xr[pi];
        }
        if (it < 7) {
            // buf^1 was last read in iteration it-1 (barrier since) -> safe
            *(float4*)&wv_s[buf ^ 1][sr][sc4] = wv_in;
            *(float4*)&xb_s[buf ^ 1][sr][sc4] = xb_in;
        }
        __syncthreads();
    }

    const int c0 = cG + threadIdx.y * 4;
    const int p0 = pG + threadIdx.x * 4;
    #pragma unroll
    for (int ci = 0; ci < 4; ci++) {
        float b = bv[c0 + ci];
        float4 v = make_float4(acc[ci][0] + b, acc[ci][1] + b,
                               acc[ci][2] + b, acc[ci][3] + b);
        #pragma unroll
        for (int f = 0; f < L; f++)
            *(float4*)&out[(size_t)(f * C + c0 + ci) * HW + p0] = v;
    }
}

// ---------------- launch -----------------------------------------------------
extern "C" void kernel_launch(void* const* d_in, const int* in_sizes, int n_in,
                              void* d_out, int out_size) {
    const float* x  = (const float*)d_in[0];
    // d_in[1]=Wq, d_in[2]=bq unused (cancel in softmax over j)
    const float* Wk = (const float*)d_in[3];
    // d_in[4]=bk unused (border bias map is j-independent -> cancels)
    const float* Wv = (const float*)d_in[5];
    const float* bv = (const float*)d_in[6];
    const float* Wa = (const float*)d_in[7];
    // d_in[8]=ba unused (cancels)
    float* out = (float*)d_out;

    // order chosen so the single ncu capture (launch index 3) profiles akb
    fold_kernel<<<25, 128>>>(Wk, Wa);                         // 0
    convh_kernel<<<dim3(HH / RPB, NPART, L), TPB>>>(x);       // 1
    transpose_wv_a<<<64, 128>>>(Wv);                          // 2
    akb_kernel<<<dim3(9, L), 256>>>();                        // 3  <- profiled
    transpose_wv_b<<<64, 128>>>(Wv);                          // 4
    xbarsm_kernel<<<dim3(9, 32), 256>>>(x);                   // 5
    gemm_out_kernel<<<dim3(HW / 64, 2), dim3(16, 16)>>>(bv, out);  // 6
}

// round 17
// speedup vs baseline: 1.1221x; 1.0204x over previous
#include <cuda_runtime.h>
#include <math.h>

#define L 16
#define C 128
#define HH 96
#define WW 96
#define HW (HH*WW)          // 9216
#define CHW (C*HW)          // 1179648

#define CG 16               // channels per group (pass A)
#define NPART (C/CG)        // 8
#define RPB 16              // rows per block
#define TPB 192             // 16 rows x 12 strips of 8 px

typedef unsigned long long ull;

// ---------------- scratch (device globals; no runtime allocation) -------------
__device__ float2 g_weff2[C*25];          // [c][k] folded conv weights, dup {w,w}
__device__ float  g_WvT[C*C];             // WvT[k][c] = Wv[c][k]
__device__ float  g_u[NPART*L*5*HW];      // partial horiz conv [part][l][kh][hw] 23.6MB
__device__ float  g_Ak[L*HW];             // pre-softmax scores [j][hw]
__device__ float  g_xbar[C*HW];           // softmax-weighted frame average [c][hw]

// ---------------- 1. fold Wk into the 25 per-tap projection vectors ----------
// weff[c][k] = sum_d Wa[C+d][k] * Wk[d][c]   (bk/ba/Wq/bq all cancel in softmax)
__global__ void fold_kernel(const float* __restrict__ Wk,
                            const float* __restrict__ Wa) {
    int k = blockIdx.x;      // 0..24
    int c = threadIdx.x;     // 0..127
    float acc = 0.f;
    #pragma unroll 4
    for (int d = 0; d < C; d++)
        acc += Wa[(C + d) * 25 + k] * Wk[d * C + c];
    g_weff2[c * 25 + k] = make_float2(acc, acc);
}

// ---------------- 2a/2b. transpose Wv (split so akb sits at capture idx 3) ---
__global__ void transpose_wv_a(const float* __restrict__ Wv) {
    int k = blockIdx.x;                // 0..63
    int c = threadIdx.x;
    g_WvT[k * C + c] = Wv[c * C + k];
}
__global__ void transpose_wv_b(const float* __restrict__ Wv) {
    int k = 64 + blockIdx.x;           // 64..127
    int c = threadIdx.x;
    g_WvT[k * C + c] = Wv[c * C + k];
}

// ---------------- 3. Pass A: fused projection + HORIZONTAL 5-tap conv --------
// u[part][l][kh][h][w] = sum_{c in part} sum_kw weff[c][kh*5+kw] * x[l][c][h][w+kw-2]
// (exact R12 configuration: 40.3us measured)
__global__ void __launch_bounds__(TPB, 4) convh_kernel(const float* __restrict__ x) {
    __shared__ ull ws2[CG * 25];   // this group's duplicated weights, 3.2 KB
    const int tid    = threadIdx.x;
    const int rowblk = blockIdx.x;      // 0..5
    const int part   = blockIdx.y;      // 0..7
    const int l      = blockIdx.z;      // 0..15
    const int row    = tid / 12;        // 0..15
    const int strip  = tid - row * 12;  // 0..11
    const int w0     = strip * 8;
    const int h      = rowblk * RPB + row;
    const int c0     = part * CG;

    const ull* wsrc = (const ull*)g_weff2;
    #pragma unroll
    for (int i = tid; i < CG * 25; i += TPB) {
        int c = i / 25, k = i - c * 25;
        ws2[i] = wsrc[(c0 + c) * 25 + k];
    }
    __syncthreads();

    ull acc[5][4];
    #pragma unroll
    for (int kh = 0; kh < 5; kh++)
        #pragma unroll
        for (int j = 0; j < 4; j++) acc[kh][j] = 0ull;

    const bool led = (strip == 0);
    const bool red = (strip == 11);
    const float* xb = x + (size_t)l * CHW + (size_t)c0 * HW + h * WW + (w0 - 2);

    #pragma unroll 2
    for (int c = 0; c < CG; c++) {
        const float* xr = xb + c * HW;
        float2 f0 = led ? make_float2(0.f, 0.f) : *(const float2*)(xr);
        float2 f1 = *(const float2*)(xr + 2);
        float2 f2 = *(const float2*)(xr + 4);
        float2 f3 = *(const float2*)(xr + 6);
        float2 f4 = *(const float2*)(xr + 8);
        float2 f5 = red ? make_float2(0.f, 0.f) : *(const float2*)(xr + 10);

        ull a[6], m[5];
        asm("mov.b64 %0, {%1, %2};" : "=l"(a[0]) : "f"(f0.x), "f"(f0.y));
        asm("mov.b64 %0, {%1, %2};" : "=l"(a[1]) : "f"(f1.x), "f"(f1.y));
        asm("mov.b64 %0, {%1, %2};" : "=l"(a[2]) : "f"(f2.x), "f"(f2.y));
        asm("mov.b64 %0, {%1, %2};" : "=l"(a[3]) : "f"(f3.x), "f"(f3.y));
        asm("mov.b64 %0, {%1, %2};" : "=l"(a[4]) : "f"(f4.x), "f"(f4.y));
        asm("mov.b64 %0, {%1, %2};" : "=l"(a[5]) : "f"(f5.x), "f"(f5.y));
        asm("mov.b64 %0, {%1, %2};" : "=l"(m[0]) : "f"(f0.y), "f"(f1.x));
        asm("mov.b64 %0, {%1, %2};" : "=l"(m[1]) : "f"(f1.y), "f"(f2.x));
        asm("mov.b64 %0, {%1, %2};" : "=l"(m[2]) : "f"(f2.y), "f"(f3.x));
        asm("mov.b64 %0, {%1, %2};" : "=l"(m[3]) : "f"(f3.y), "f"(f4.x));
        asm("mov.b64 %0, {%1, %2};" : "=l"(m[4]) : "f"(f4.y), "f"(f5.x));

        const ull* wc = &ws2[c * 25];
        #pragma unroll
        for (int kh = 0; kh < 5; kh++) {
            ull w0v = wc[kh * 5 + 0];
            ull w1v = wc[kh * 5 + 1];
            ull w2v = wc[kh * 5 + 2];
            ull w3v = wc[kh * 5 + 3];
            ull w4v = wc[kh * 5 + 4];
            #pragma unroll
            for (int j = 0; j < 4; j++) {
                asm("fma.rn.f32x2 %0, %1, %2, %0;" : "+l"(acc[kh][j]) : "l"(w0v), "l"(a[j]));
                asm("fma.rn.f32x2 %0, %1, %2, %0;" : "+l"(acc[kh][j]) : "l"(w1v), "l"(m[j]));
                asm("fma.rn.f32x2 %0, %1, %2, %0;" : "+l"(acc[kh][j]) : "l"(w2v), "l"(a[j + 1]));
                asm("fma.rn.f32x2 %0, %1, %2, %0;" : "+l"(acc[kh][j]) : "l"(w3v), "l"(m[j + 1]));
                asm("fma.rn.f32x2 %0, %1, %2, %0;" : "+l"(acc[kh][j]) : "l"(w4v), "l"(a[j + 2]));
            }
        }
    }

    float* ub = g_u + (((size_t)part * L + l) * 5) * HW + h * WW + w0;
    #pragma unroll
    for (int kh = 0; kh < 5; kh++) {
        #pragma unroll
        for (int j = 0; j < 4; j++) {
            float lo, hi;
            asm("mov.b64 {%0, %1}, %2;" : "=f"(lo), "=f"(hi) : "l"(acc[kh][j]));
            *(float2*)(ub + kh * HW + 2 * j) = make_float2(lo, hi);
        }
    }
}

// ---------------- 4. Pass B: vertical 5-tap + partial-sum -> Ak --------------
// ONE pixel per thread: 576 blocks (~31 warps/SM) with 40 independent scalar
// loads each -> latency fully hidden (the 4px/thread version was 144 blocks,
// occ 11.5%, issue 4%, 11.2us measured).
__global__ void akb_kernel() {
    const int l  = blockIdx.y;
    const int hw = blockIdx.x * 256 + threadIdx.x;
    const int h  = hw / WW;
    const int w  = hw - h * WW;

    float acc = 0.f;
    #pragma unroll
    for (int kh = 0; kh < 5; kh++) {
        const int hh = h + kh - 2;
        if ((unsigned)hh >= HH) continue;
        const float* up = g_u + (size_t)l * 5 * HW + kh * HW + hh * WW + w;
        #pragma unroll
        for (int part = 0; part < NPART; part++)
            acc += up[(size_t)part * L * 5 * HW];
    }
    g_Ak[l * HW + hw] = acc;
}

// ---------------- 5. fused softmax + xbar ------------------------------------
__global__ void xbarsm_kernel(const float* __restrict__ x) {
    const int p4    = blockIdx.x * 1024 + threadIdx.x * 4;   // pixel base
    const int cbase = blockIdx.y * 4;

    float4 a[L];
    #pragma unroll
    for (int j = 0; j < L; j++)
        a[j] = *(const float4*)&g_Ak[j * HW + p4];

    float4 mx = a[0];
    #pragma unroll
    for (int j = 1; j < L; j++) {
        mx.x = fmaxf(mx.x, a[j].x); mx.y = fmaxf(mx.y, a[j].y);
        mx.z = fmaxf(mx.z, a[j].z); mx.w = fmaxf(mx.w, a[j].w);
    }
    float4 s = make_float4(0.f, 0.f, 0.f, 0.f);
    #pragma unroll
    for (int j = 0; j < L; j++) {
        a[j].x = __expf(a[j].x - mx.x); s.x += a[j].x;
        a[j].y = __expf(a[j].y - mx.y); s.y += a[j].y;
        a[j].z = __expf(a[j].z - mx.z); s.z += a[j].z;
        a[j].w = __expf(a[j].w - mx.w); s.w += a[j].w;
    }
    const float4 inv = make_float4(1.f / s.x, 1.f / s.y, 1.f / s.z, 1.f / s.w);

    float4 acc[4];
    #pragma unroll
    for (int i = 0; i < 4; i++) acc[i] = make_float4(0.f, 0.f, 0.f, 0.f);

    #pragma unroll
    for (int j = 0; j < L; j++) {
        const float* xj = x + (size_t)(j * C + cbase) * HW + p4;
        #pragma unroll
        for (int i = 0; i < 4; i++) {
            const float4 xv = *(const float4*)&xj[i * HW];
            acc[i].x += a[j].x * xv.x;
            acc[i].y += a[j].y * xv.y;
            acc[i].z += a[j].z * xv.z;
            acc[i].w += a[j].w * xv.w;
        }
    }
    #pragma unroll
    for (int i = 0; i < 4; i++) {
        float4 r = make_float4(acc[i].x * inv.x, acc[i].y * inv.y,
                               acc[i].z * inv.z, acc[i].w * inv.w);
        *(float4*)&g_xbar[(cbase + i) * HW + p4] = r;
    }
}

// ---------------- 6. out[f][c][hw] = Wv . xbar + bv, broadcast to 16 frames --
// Double-buffered k-loop (measured improvement over the serial R12 version).
__global__ void gemm_out_kernel(const float* __restrict__ bv,
                                float* __restrict__ out) {
    __shared__ float wv_s[2][16][64];
    __shared__ float xb_s[2][16][64];
    const int tid = threadIdx.y * 16 + threadIdx.x;
    const int pG = blockIdx.x * 64;
    const int cG = blockIdx.y * 64;

    const int sr   = tid >> 4;          // 0..15
    const int sc4  = (tid & 15) * 4;    // 0..60

    // preload stage 0
    float4 wv_in = *(const float4*)&g_WvT[sr * C + cG + sc4];
    float4 xb_in = *(const float4*)&g_xbar[sr * HW + pG + sc4];
    *(float4*)&wv_s[0][sr][sc4] = wv_in;
    *(float4*)&xb_s[0][sr][sc4] = xb_in;
    __syncthreads();

    float acc[4][4];
    #pragma unroll
    for (int i = 0; i < 4; i++)
        #pragma unroll
        for (int j = 0; j < 4; j++) acc[i][j] = 0.f;

    #pragma unroll
    for (int it = 0; it < 8; it++) {
        const int buf = it & 1;
        if (it < 7) {
            const int k0 = (it + 1) * 16;
            wv_in = *(const float4*)&g_WvT[(k0 + sr) * C + cG + sc4];
            xb_in = *(const float4*)&g_xbar[(k0 + sr) * HW + pG + sc4];
        }
        #pragma unroll
        for (int kk = 0; kk < 16; kk++) {
            const float4 wv4 = *(const float4*)&wv_s[buf][kk][threadIdx.y * 4];
            const float4 xb4 = *(const float4*)&xb_s[buf][kk][threadIdx.x * 4];
            float wr[4] = {wv4.x, wv4.y, wv4.z, wv4.w};
            float xr[4] = {xb4.x, xb4.y, xb4.z, xb4.w};
            #pragma unroll
            for (int ci = 0; ci < 4; ci++)
                #pragma unroll
                for (int pi = 0; pi < 4; pi++)
                    acc[ci][pi] += wr[ci] * xr[pi];
        }
        if (it < 7) {
            *(float4*)&wv_s[buf ^ 1][sr][sc4] = wv_in;
            *(float4*)&xb_s[buf ^ 1][sr][sc4] = xb_in;
        }
        __syncthreads();
    }

    const int c0 = cG + threadIdx.y * 4;
    const int p0 = pG + threadIdx.x * 4;
    #pragma unroll
    for (int ci = 0; ci < 4; ci++) {
        float b = bv[c0 + ci];
        float4 v = make_float4(acc[ci][0] + b, acc[ci][1] + b,
                               acc[ci][2] + b, acc[ci][3] + b);
        #pragma unroll
        for (int f = 0; f < L; f++)
            *(float4*)&out[(size_t)(f * C + c0 + ci) * HW + p0] = v;
    }
}

// ---------------- launch -----------------------------------------------------
extern "C" void kernel_launch(void* const* d_in, const int* in_sizes, int n_in,
                              void* d_out, int out_size) {
    const float* x  = (const float*)d_in[0];
    // d_in[1]=Wq, d_in[2]=bq unused (cancel in softmax over j)
    const float* Wk = (const float*)d_in[3];
    // d_in[4]=bk unused (border bias map is j-independent -> cancels)
    const float* Wv = (const float*)d_in[5];
    const float* bv = (const float*)d_in[6];
    const float* Wa = (const float*)d_in[7];
    // d_in[8]=ba unused (cancels)
    float* out = (float*)d_out;

    // order chosen so the single ncu capture (launch index 3) profiles akb
    fold_kernel<<<25, 128>>>(Wk, Wa);                         // 0
    convh_kernel<<<dim3(HH / RPB, NPART, L), TPB>>>(x);       // 1
    transpose_wv_a<<<64, 128>>>(Wv);                          // 2
    akb_kernel<<<dim3(36, L), 256>>>();                       // 3  <- profiled (576 blocks)
    transpose_wv_b<<<64, 128>>>(Wv);                          // 4
    xbarsm_kernel<<<dim3(9, 32), 256>>>(x);                   // 5
    gemm_out_kernel<<<dim3(HW / 64, 2), dim3(16, 16)>>>(bv, out);  // 6
}